// round 1
// baseline (speedup 1.0000x reference)
#include <cuda_runtime.h>
#include <math.h>

// Input order per reference setup_inputs():
//   d_in[0] image_features1 [4096,256] f32
//   d_in[1] image_features2 [4096,256] f32
//   d_in[2] logit_scale     [1]        f32
//   d_in[3] memory_bank1    [16384,256] f32 (already unit-norm)
//   d_in[4] memory_bank2    [16384,256] f32 (already unit-norm)
// Output: scalar f32.

namespace {
constexpr int NB   = 4096;
constexpr int NC   = 256;
constexpr int NM   = 16384;
constexpr int NCOL = NB + NM;       // 20480
constexpr int TM   = 128;
constexpr int TN   = 128;
constexpr int BK   = 32;
constexpr int CHUNK = 2048;
constexpr int NCH  = NCOL / CHUNK;  // 10 (chunks 0,1 = cross-view features, 2..9 = bank)
}

// Scratch (device globals: no allocations allowed)
__device__ float g_f1[NB * NC];
__device__ float g_f2[NB * NC];
__device__ float g_s[2][NB][NCH];     // per (dir,row,chunk) sum of exp(scale*(v-1))
__device__ float g_bmax[2][NB][NCH];  // per-chunk bank max similarity
__device__ float g_diag[2][NB];       // label logit per row

__device__ __forceinline__ void ffma2(unsigned long long& d,
                                      unsigned long long a,
                                      unsigned long long b) {
    asm("fma.rn.f32x2 %0, %1, %2, %0;" : "+l"(d) : "l"(a), "l"(b));
}
__device__ __forceinline__ void unpack2(unsigned long long d, float& x, float& y) {
    asm("mov.b64 {%0, %1}, %2;" : "=f"(x), "=f"(y) : "l"(d));
}

// ---------------------------------------------------------------------------
// Kernel 1: L2-normalize both feature sets. One warp per row (256 floats).
// ---------------------------------------------------------------------------
__global__ void knorm(const float* __restrict__ in1, const float* __restrict__ in2) {
    int gw   = (blockIdx.x * blockDim.x + threadIdx.x) >> 5;
    int lane = threadIdx.x & 31;
    if (gw >= 2 * NB) return;
    const float* src; float* dst; int row;
    if (gw < NB) { src = in1; dst = g_f1; row = gw; }
    else         { src = in2; dst = g_f2; row = gw - NB; }

    const float4* s4 = (const float4*)(src + (size_t)row * NC);
    float4 v0 = s4[lane];
    float4 v1 = s4[lane + 32];
    float ss = v0.x*v0.x + v0.y*v0.y + v0.z*v0.z + v0.w*v0.w
             + v1.x*v1.x + v1.y*v1.y + v1.z*v1.z + v1.w*v1.w;
    #pragma unroll
    for (int o = 16; o > 0; o >>= 1) ss += __shfl_xor_sync(0xffffffffu, ss, o);
    float inv = 1.0f / fmaxf(sqrtf(ss), 1e-12f);

    v0.x *= inv; v0.y *= inv; v0.z *= inv; v0.w *= inv;
    v1.x *= inv; v1.y *= inv; v1.z *= inv; v1.w *= inv;
    float4* d4 = (float4*)(dst + (size_t)row * NC);
    d4[lane]      = v0;
    d4[lane + 32] = v1;
}

// ---------------------------------------------------------------------------
// Kernel 2: fused GEMM + lse-sum + bank-max + diag extraction.
// Grid: (chunk 0..9, rowtile 0..31, dir 0..1). 256 threads, 128x128 tile,
// 8x8 micro-tile per thread, FFMA2 packed fp32 (pairs along N).
// ---------------------------------------------------------------------------
__global__ void __launch_bounds__(256) kgemm(const float* __restrict__ mb1,
                                             const float* __restrict__ mb2,
                                             const float* __restrict__ scale_ptr) {
    const int chunk = blockIdx.x;
    const int rowt  = blockIdx.y;
    const int dir   = blockIdx.z;
    const float* A      = (dir == 0) ? g_f1 : g_f2;
    const float* otherF = (dir == 0) ? g_f2 : g_f1;
    const float* bank   = (dir == 0) ? mb2  : mb1;
    const float scale   = *scale_ptr;

    const int tid   = threadIdx.x;
    const int tx    = tid & 15;
    const int ty    = tid >> 4;
    const int rbase = ty * 8;
    const int cbase = tx * 8;
    const int rowg0 = rowt * TM;

    // As2 holds each A value duplicated in adjacent slots so the FFMA2
    // broadcast operand is a single aligned 64-bit shared load.
    __shared__ float As2[BK][2 * TM];   // 32 KB
    __shared__ float Bs[BK][TN];        // 16 KB  (total 48 KB static)

    float s_acc[8];
    float bmax[8];
    #pragma unroll
    for (int r = 0; r < 8; r++) { s_acc[r] = 0.0f; bmax[r] = -2.0f; }

    const bool isBank = (chunk >= 2);
    const float* Bbase = isBank
        ? (bank   + (size_t)(chunk * CHUNK - NB) * NC)
        : (otherF + (size_t)(chunk * CHUNK) * NC);
    const float* Atile = A + (size_t)rowg0 * NC;

    for (int tile = 0; tile < CHUNK / TN; ++tile) {
        unsigned long long acc[8][4];
        #pragma unroll
        for (int r = 0; r < 8; r++)
            #pragma unroll
            for (int p = 0; p < 4; p++) acc[r][p] = 0ull;

        const float* Btile = Bbase + (size_t)tile * TN * NC;

        #pragma unroll 1
        for (int kk = 0; kk < NC; kk += BK) {
            // Cooperative load: 1024 float4 each for A and B, 4 per thread.
            #pragma unroll
            for (int it = 0; it < 4; ++it) {
                int idx = tid + it * 256;
                int r   = idx >> 3;
                int k4  = (idx & 7) * 4;
                float4 va = *(const float4*)(Atile + (size_t)r * NC + kk + k4);
                As2[k4 + 0][2*r] = va.x; As2[k4 + 0][2*r + 1] = va.x;
                As2[k4 + 1][2*r] = va.y; As2[k4 + 1][2*r + 1] = va.y;
                As2[k4 + 2][2*r] = va.z; As2[k4 + 2][2*r + 1] = va.z;
                As2[k4 + 3][2*r] = va.w; As2[k4 + 3][2*r + 1] = va.w;
                float4 vb = *(const float4*)(Btile + (size_t)r * NC + kk + k4);
                Bs[k4 + 0][r] = vb.x;
                Bs[k4 + 1][r] = vb.y;
                Bs[k4 + 2][r] = vb.z;
                Bs[k4 + 3][r] = vb.w;
            }
            __syncthreads();

            #pragma unroll
            for (int k = 0; k < BK; ++k) {
                ulonglong2 a01 = *(const ulonglong2*)&As2[k][2 * rbase + 0];
                ulonglong2 a23 = *(const ulonglong2*)&As2[k][2 * rbase + 4];
                ulonglong2 a45 = *(const ulonglong2*)&As2[k][2 * rbase + 8];
                ulonglong2 a67 = *(const ulonglong2*)&As2[k][2 * rbase + 12];
                ulonglong2 b01 = *(const ulonglong2*)&Bs[k][cbase + 0];
                ulonglong2 b23 = *(const ulonglong2*)&Bs[k][cbase + 4];
                unsigned long long ap[8] = {a01.x, a01.y, a23.x, a23.y,
                                            a45.x, a45.y, a67.x, a67.y};
                unsigned long long bp[4] = {b01.x, b01.y, b23.x, b23.y};
                #pragma unroll
                for (int r = 0; r < 8; r++) {
                    #pragma unroll
                    for (int p = 0; p < 4; p++) ffma2(acc[r][p], ap[r], bp[p]);
                }
            }
            __syncthreads();
        }

        // Epilogue: logits never stored; fold into exp-sum / bank-max / diag.
        int colg0 = chunk * CHUNK + tile * TN + cbase;
        #pragma unroll
        for (int r = 0; r < 8; r++) {
            int rowg = rowg0 + rbase + r;
            #pragma unroll
            for (int p = 0; p < 4; p++) {
                float v0, v1;
                unpack2(acc[r][p], v0, v1);
                int cg = colg0 + 2 * p;
                // logsumexp with fixed max = scale (cos <= 1 for unit vectors)
                s_acc[r] += __expf(fmaf(scale, v0, -scale));
                s_acc[r] += __expf(fmaf(scale, v1, -scale));
                if (isBank) {
                    if (v0 > bmax[r]) bmax[r] = v0;
                    if (v1 > bmax[r]) bmax[r] = v1;
                } else {
                    if (cg     == rowg) g_diag[dir][rowg] = scale * v0;
                    if (cg + 1 == rowg) g_diag[dir][rowg] = scale * v1;
                }
            }
        }
    }

    // Cross-thread (tx) merge per row, overlaying As2 as scratch.
    __syncthreads();
    float* sBuf = &As2[0][0];     // 2048 floats
    float* mBuf = sBuf + 2048;    // 2048 floats (As2 has 8192 total)
    #pragma unroll
    for (int r = 0; r < 8; r++) {
        int row = rbase + r;
        sBuf[row * 16 + tx] = s_acc[r];
        mBuf[row * 16 + tx] = bmax[r];
    }
    __syncthreads();
    if (tid < TM) {
        int row = tid;
        float t = 0.0f, bm = -2.0f;
        #pragma unroll
        for (int j = 0; j < 16; j++) {
            t += sBuf[row * 16 + j];
            bm = fmaxf(bm, mBuf[row * 16 + j]);
        }
        int rg = rowg0 + row;
        g_s[dir][rg][chunk]    = t;
        g_bmax[dir][rg][chunk] = bm;
    }
}

// ---------------------------------------------------------------------------
// Kernel 3: merge chunks, compute CE rows + ICEL, reduce to scalar.
// sq = ||f - bank[nn]||^2 = 2 - 2*max_sim (unit vectors) -> no gather needed.
// ---------------------------------------------------------------------------
__global__ void kfinal(const float* __restrict__ scale_ptr, float* __restrict__ out) {
    const float scale = *scale_ptr;
    int tid = threadIdx.x;
    float nce_sum = 0.0f, s1 = 0.0f, c1 = 0.0f, s2 = 0.0f, c2 = 0.0f;

    for (int idx = tid; idx < 2 * NB; idx += 256) {
        int dir = idx >> 12;          // NB = 4096 = 2^12
        int row = idx & (NB - 1);
        float t = 0.0f;
        #pragma unroll
        for (int ch = 0; ch < NCH; ch++) t += g_s[dir][row][ch];
        nce_sum += scale + logf(t) - g_diag[dir][row];

        float bm = -2.0f;
        #pragma unroll
        for (int ch = 2; ch < NCH; ch++) bm = fmaxf(bm, g_bmax[dir][row][ch]);
        if (bm > 0.2f) {
            float sq = 2.0f - 2.0f * bm;
            if (dir == 0) { s1 += sq; c1 += 1.0f; }
            else          { s2 += sq; c2 += 1.0f; }
        }
    }

    __shared__ float red[5][256];
    red[0][tid] = nce_sum; red[1][tid] = s1; red[2][tid] = c1;
    red[3][tid] = s2;      red[4][tid] = c2;
    __syncthreads();
    for (int o = 128; o > 0; o >>= 1) {
        if (tid < o) {
            #pragma unroll
            for (int q = 0; q < 5; q++) red[q][tid] += red[q][tid + o];
        }
        __syncthreads();
    }
    if (tid == 0) {
        float nce = 0.5f * red[0][0] / (float)NB;  // 0.5*(mean1+mean2)
        float i1  = (red[2][0] > 0.0f) ? red[1][0] / (red[2][0] * (float)NC) : 0.0f;
        float i2  = (red[4][0] > 0.0f) ? red[3][0] / (red[4][0] * (float)NC) : 0.0f;
        out[0] = nce + 0.5f * (0.5f * (i1 + i2));  // LAMBDA_ICEL * icel
    }
}

// ---------------------------------------------------------------------------
extern "C" void kernel_launch(void* const* d_in, const int* in_sizes, int n_in,
                              void* d_out, int out_size) {
    const float* if1 = (const float*)d_in[0];
    const float* if2 = (const float*)d_in[1];
    const float* sc  = (const float*)d_in[2];
    const float* mb1 = (const float*)d_in[3];
    const float* mb2 = (const float*)d_in[4];
    float* out = (float*)d_out;

    knorm<<<(2 * NB * 32) / 256, 256>>>(if1, if2);
    dim3 grid(NCH, NB / TM, 2);
    kgemm<<<grid, 256>>>(mb1, mb2, sc);
    kfinal<<<1, 256>>>(sc, out);
}

// round 3
// speedup vs baseline: 10.9545x; 10.9545x over previous
#include <cuda_runtime.h>
#include <cuda_bf16.h>
#include <cstdint>
#include <math.h>

// Inputs: [0] if1 [4096,256] f32, [1] if2, [2] scale [1], [3] mb1 [16384,256] f32 (unit rows), [4] mb2
// Output: scalar f32.

namespace {
constexpr int NB = 4096, NC = 256, NM = 16384;
constexpr int TM = 128, TN = 128;
constexpr int NT = 80;              // B tiles per CTA (10240 / 128)
constexpr int HALFCOLS = 10240;
constexpr int ROWB = 512;           // bytes per K-major row (256 bf16)
constexpr int TILEB = TM * ROWB;    // 64 KB
constexpr int SMEM_DYN = 1024 + 3 * TILEB;  // align pad + A + B0 + B1
}

// Device-global scratch (no allocations allowed)
__device__ __nv_bfloat16 g_f1h[NB * NC];
__device__ __nv_bfloat16 g_f2h[NB * NC];
__device__ __nv_bfloat16 g_mb1h[NM * NC];
__device__ __nv_bfloat16 g_mb2h[NM * NC];
__device__ float g_s[2][NB][2];      // exp-sum per (dir,row,colhalf)
__device__ float g_bmax[2][NB][2];   // bank max-sim per (dir,row,colhalf)
__device__ float g_diag[2][NB];

// ---------------- PTX helpers (all plain sm_80+-class, no 'a' features) ----
__device__ __forceinline__ uint32_t smem_u32(const void* p) {
    uint32_t a;
    asm("{ .reg .u64 t; cvta.to.shared.u64 t, %1; cvt.u32.u64 %0, t; }" : "=r"(a) : "l"(p));
    return a;
}
__device__ __forceinline__ void cp16(uint32_t d, const void* s) {
    asm volatile("cp.async.cg.shared.global [%0], [%1], 16;" :: "r"(d), "l"(s) : "memory");
}
__device__ __forceinline__ void cp_commit()  { asm volatile("cp.async.commit_group;" ::: "memory"); }
__device__ __forceinline__ void cp_wait1()   { asm volatile("cp.async.wait_group 1;" ::: "memory"); }
__device__ __forceinline__ void cp_wait0()   { asm volatile("cp.async.wait_group 0;" ::: "memory"); }
__device__ __forceinline__ void ldsm4(uint32_t& r0, uint32_t& r1, uint32_t& r2, uint32_t& r3,
                                      uint32_t addr) {
    asm volatile("ldmatrix.sync.aligned.m8n8.x4.shared.b16 {%0,%1,%2,%3}, [%4];"
                 : "=r"(r0), "=r"(r1), "=r"(r2), "=r"(r3) : "r"(addr));
}
__device__ __forceinline__ void mma16816(float* c, const uint32_t* a, const uint32_t* b) {
    asm volatile(
        "mma.sync.aligned.m16n8k16.row.col.f32.bf16.bf16.f32 "
        "{%0,%1,%2,%3}, {%4,%5,%6,%7}, {%8,%9}, {%0,%1,%2,%3};"
        : "+f"(c[0]), "+f"(c[1]), "+f"(c[2]), "+f"(c[3])
        : "r"(a[0]), "r"(a[1]), "r"(a[2]), "r"(a[3]), "r"(b[0]), "r"(b[1]));
}
__device__ __forceinline__ float ex2f(float x) {
    float e; asm("ex2.approx.f32 %0, %1;" : "=f"(e) : "f"(x)); return e;
}

// ---------------------------------------------------------------------------
// Prep: normalize features -> bf16; convert banks -> bf16. One warp per row.
// ---------------------------------------------------------------------------
__global__ void kprep(const float* __restrict__ in1, const float* __restrict__ in2,
                      const float* __restrict__ b1, const float* __restrict__ b2) {
    int gw = (blockIdx.x * blockDim.x + threadIdx.x) >> 5;
    int lane = threadIdx.x & 31;
    const float* src; __nv_bfloat16* dst; bool donorm; int row;
    if (gw < NB)               { src = in1; dst = g_f1h;  row = gw;               donorm = true; }
    else if (gw < 2 * NB)      { src = in2; dst = g_f2h;  row = gw - NB;          donorm = true; }
    else if (gw < 2 * NB + NM) { src = b1;  dst = g_mb1h; row = gw - 2 * NB;      donorm = false; }
    else                       { src = b2;  dst = g_mb2h; row = gw - 2 * NB - NM; donorm = false; }

    const float4* s4 = (const float4*)(src + (size_t)row * NC);
    float4 v0 = s4[lane * 2], v1 = s4[lane * 2 + 1];
    float inv = 1.0f;
    if (donorm) {
        float ss = v0.x*v0.x + v0.y*v0.y + v0.z*v0.z + v0.w*v0.w
                 + v1.x*v1.x + v1.y*v1.y + v1.z*v1.z + v1.w*v1.w;
        #pragma unroll
        for (int o = 16; o > 0; o >>= 1) ss += __shfl_xor_sync(0xffffffffu, ss, o);
        inv = 1.0f / fmaxf(sqrtf(ss), 1e-12f);
    }
    __nv_bfloat162 p0 = __floats2bfloat162_rn(v0.x * inv, v0.y * inv);
    __nv_bfloat162 p1 = __floats2bfloat162_rn(v0.z * inv, v0.w * inv);
    __nv_bfloat162 p2 = __floats2bfloat162_rn(v1.x * inv, v1.y * inv);
    __nv_bfloat162 p3 = __floats2bfloat162_rn(v1.z * inv, v1.w * inv);
    uint4 o;
    o.x = *(uint32_t*)&p0; o.y = *(uint32_t*)&p1; o.z = *(uint32_t*)&p2; o.w = *(uint32_t*)&p3;
    ((uint4*)(dst + (size_t)row * NC))[lane] = o;
}

// ---------------------------------------------------------------------------
// Fused GEMM (mma.sync bf16) + exp-sum + bank-max + diag.
// Grid (colhalf 0..1, rowtile 0..31, dir 0..1) = 128 CTAs, 256 threads.
// Warp layout: wm = wid&1 (2 along M, 64 rows), wn = wid>>1 (4 along N, 32 cols).
// Smem: A 128x256 bf16 resident; B double-buffered; K-major rows, 16B-chunk
// XOR swizzle (off ^ ((row&7)<<4)) for conflict-free ldmatrix.
// ---------------------------------------------------------------------------
__global__ void __launch_bounds__(256, 1) kgemm(const float* __restrict__ scale_ptr) {
    extern __shared__ char dsm[];
    const uint32_t raw  = smem_u32(dsm);
    const uint32_t base = (raw + 1023u) & ~1023u;
    const uint32_t aBase = base;
    const uint32_t bBase0 = base + TILEB;
    const uint32_t bBase1 = base + 2 * TILEB;
    char* smA = dsm + (base - raw);     // generic pointer to aligned region

    const int tid = threadIdx.x, wid = tid >> 5, lane = tid & 31;
    const int half = blockIdx.x, rowt = blockIdx.y, dir = blockIdx.z;
    const int rowg0 = rowt * TM;
    const int wm = wid & 1, wn = wid >> 1;
    const __nv_bfloat16* Af = dir ? g_f2h : g_f1h;
    const __nv_bfloat16* Fo = dir ? g_f1h : g_f2h;
    const __nv_bfloat16* Bk = dir ? g_mb1h : g_mb2h;
    const float scale = *scale_ptr;
    const float cl2 = scale * 1.4426950408889634f;   // scale*log2(e)

    auto loadTile = [&](uint32_t smemBase, const char* src) {
        #pragma unroll
        for (int t = 0; t < 16; t++) {
            int idx = tid + t * 256;
            int r   = idx >> 5;
            uint32_t kb = (uint32_t)((idx & 31) * 16);
            cp16(smemBase + (uint32_t)r * ROWB + (kb ^ (uint32_t)((r & 7) << 4)),
                 src + (size_t)r * ROWB + kb);
        }
    };
    auto bSrc = [&](int i) -> const char* {
        int colg0 = half * HALFCOLS + i * TN;
        return (colg0 < NB) ? (const char*)(Fo + (size_t)colg0 * NC)
                            : (const char*)(Bk + (size_t)(colg0 - NB) * NC);
    };

    // Group 0: A tile + B tile 0
    loadTile(aBase, (const char*)(Af + (size_t)rowg0 * NC));
    loadTile(bBase0, bSrc(0));
    cp_commit();

    // Per-thread ldmatrix address components.
    const int r8 = lane & 7;
    const uint32_t sw = (uint32_t)(r8 << 4);
    const int aRow = wm * 64 + r8 + ((lane >> 3) & 1) * 8;  // + mf*16
    const uint32_t aKsel = (uint32_t)(((lane >> 4) & 1) * 16);
    const int bRow = wn * 32 + r8 + ((lane >> 4) & 1) * 8;  // + nfp*16
    const uint32_t bKsel = (uint32_t)(((lane >> 3) & 1) * 16);
    uint32_t aAddr[4];
    #pragma unroll
    for (int mf = 0; mf < 4; mf++) aAddr[mf] = aBase + (uint32_t)(aRow + mf * 16) * ROWB;

    float s_acc[8], bmax[8];
    #pragma unroll
    for (int q = 0; q < 8; q++) { s_acc[q] = 0.0f; bmax[q] = -2.0f; }

    #pragma unroll 1
    for (int i = 0; i < NT; i++) {
        if (i + 1 < NT) {
            loadTile((i & 1) ? bBase0 : bBase1, bSrc(i + 1));
            cp_commit();
            cp_wait1();
        } else {
            cp_wait0();
        }
        __syncthreads();

        const uint32_t bb = (i & 1) ? bBase1 : bBase0;
        const uint32_t bAddr0 = bb + (uint32_t)bRow * ROWB;
        const uint32_t bAddr1 = bAddr0 + 16u * ROWB;

        float c[4][4][4];
        #pragma unroll
        for (int mf = 0; mf < 4; mf++)
            #pragma unroll
            for (int nf = 0; nf < 4; nf++)
                #pragma unroll
                for (int e = 0; e < 4; e++) c[mf][nf][e] = 0.0f;

        #pragma unroll
        for (int ks = 0; ks < 16; ks++) {
            const uint32_t offA = ((uint32_t)(ks * 32) + aKsel) ^ sw;
            const uint32_t offB = ((uint32_t)(ks * 32) + bKsel) ^ sw;
            uint32_t a[4][4], b[4][2];
            #pragma unroll
            for (int mf = 0; mf < 4; mf++)
                ldsm4(a[mf][0], a[mf][1], a[mf][2], a[mf][3], aAddr[mf] + offA);
            ldsm4(b[0][0], b[0][1], b[1][0], b[1][1], bAddr0 + offB);
            ldsm4(b[2][0], b[2][1], b[3][0], b[3][1], bAddr1 + offB);
            #pragma unroll
            for (int mf = 0; mf < 4; mf++)
                #pragma unroll
                for (int nf = 0; nf < 4; nf++)
                    mma16816(c[mf][nf], a[mf], b[nf]);
        }

        // Epilogue on register fragments.
        const int colg0 = half * HALFCOLS + i * TN;
        const bool isBank = colg0 >= NB;
        const bool diagT = (!isBank) && (colg0 == rowg0);
        #pragma unroll
        for (int mf = 0; mf < 4; mf++) {
            #pragma unroll
            for (int nf = 0; nf < 4; nf++) {
                #pragma unroll
                for (int e = 0; e < 4; e++) {
                    float v = c[mf][nf][e];
                    int ri = mf * 2 + (e >> 1);
                    s_acc[ri] += ex2f(fmaf(cl2, v, -cl2));
                    if (isBank) {
                        bmax[ri] = fmaxf(bmax[ri], v);
                    } else if (diagT) {
                        int row_l = wm * 64 + mf * 16 + (lane >> 2) + 8 * (e >> 1);
                        int col_l = wn * 32 + nf * 8 + 2 * (lane & 3) + (e & 1);
                        if (row_l == col_l) g_diag[dir][rowg0 + row_l] = scale * v;
                    }
                }
            }
        }
        __syncthreads();   // compute done before next prefetch overwrites buffer
    }

    // Reduce: 4 threads (lane&3) share a row -> shfl; then 4 wn warps via smem.
    float* scrS = (float*)(smA + TILEB);        // overlay B0 (done with it)
    float* scrM = scrS + 512;
    #pragma unroll
    for (int q = 0; q < 8; q++) {
        float s = s_acc[q], m = bmax[q];
        s += __shfl_xor_sync(0xffffffffu, s, 1);
        s += __shfl_xor_sync(0xffffffffu, s, 2);
        m = fmaxf(m, __shfl_xor_sync(0xffffffffu, m, 1));
        m = fmaxf(m, __shfl_xor_sync(0xffffffffu, m, 2));
        if ((lane & 3) == 0) {
            int row_l = wm * 64 + (q >> 1) * 16 + (q & 1) * 8 + (lane >> 2);
            scrS[wn * 128 + row_l] = s;
            scrM[wn * 128 + row_l] = m;
        }
    }
    __syncthreads();
    if (tid < TM) {
        float s = scrS[tid] + scrS[128 + tid] + scrS[256 + tid] + scrS[384 + tid];
        float m = fmaxf(fmaxf(scrM[tid], scrM[128 + tid]),
                        fmaxf(scrM[256 + tid], scrM[384 + tid]));
        g_s[dir][rowg0 + tid][half]    = s;
        g_bmax[dir][rowg0 + tid][half] = m;
    }
}

// ---------------------------------------------------------------------------
// Final scalar reduction. sq = 2 - 2*max_sim (unit vectors) -> no gather.
// ---------------------------------------------------------------------------
__global__ void kfinal(const float* __restrict__ scale_ptr, float* __restrict__ out) {
    const float scale = *scale_ptr;
    int tid = threadIdx.x;
    float nce_sum = 0.0f, s1 = 0.0f, c1n = 0.0f, s2 = 0.0f, c2n = 0.0f;

    for (int idx = tid; idx < 2 * NB; idx += 256) {
        int dir = idx >> 12;
        int row = idx & (NB - 1);
        float t = g_s[dir][row][0] + g_s[dir][row][1];
        nce_sum += scale + logf(t) - g_diag[dir][row];
        float bm = fmaxf(g_bmax[dir][row][0], g_bmax[dir][row][1]);
        if (bm > 0.2f) {
            float sq = 2.0f - 2.0f * bm;
            if (dir == 0) { s1 += sq; c1n += 1.0f; }
            else          { s2 += sq; c2n += 1.0f; }
        }
    }

    __shared__ float red[5][256];
    red[0][tid] = nce_sum; red[1][tid] = s1; red[2][tid] = c1n;
    red[3][tid] = s2;      red[4][tid] = c2n;
    __syncthreads();
    for (int o = 128; o > 0; o >>= 1) {
        if (tid < o) {
            #pragma unroll
            for (int q = 0; q < 5; q++) red[q][tid] += red[q][tid + o];
        }
        __syncthreads();
    }
    if (tid == 0) {
        float nce = 0.5f * red[0][0] / (float)NB;
        float i1 = (red[2][0] > 0.0f) ? red[1][0] / (red[2][0] * (float)NC) : 0.0f;
        float i2 = (red[4][0] > 0.0f) ? red[3][0] / (red[4][0] * (float)NC) : 0.0f;
        out[0] = nce + 0.5f * (0.5f * (i1 + i2));
    }
}

// ---------------------------------------------------------------------------
extern "C" void kernel_launch(void* const* d_in, const int* in_sizes, int n_in,
                              void* d_out, int out_size) {
    const float* if1 = (const float*)d_in[0];
    const float* if2 = (const float*)d_in[1];
    const float* sc  = (const float*)d_in[2];
    const float* mb1 = (const float*)d_in[3];
    const float* mb2 = (const float*)d_in[4];
    float* out = (float*)d_out;

    cudaFuncSetAttribute(kgemm, cudaFuncAttributeMaxDynamicSharedMemorySize, SMEM_DYN);

    int totalWarps = 2 * NB + 2 * NM;   // 40960 rows, one warp each
    kprep<<<totalWarps / 8, 256>>>(if1, if2, mb1, mb2);
    kgemm<<<dim3(2, NB / TM, 2), 256, SMEM_DYN>>>(sc);
    kfinal<<<1, 256>>>(sc, out);
}